// round 8
// baseline (speedup 1.0000x reference)
#include <cuda_runtime.h>
#include <cuda_bf16.h>

// Problem constants (fixed by the reference)
#define NNODES 50000
#define NEDGES 800000
#define D      64
#define NCLS   16

// Scratch (device globals)
__device__ float4 g_t1[NNODES * NCLS / 4];   // M1 x
__device__ float4 g_u2[NNODES * NCLS / 4];   // M2 x
__device__ float4 g_u3[NNODES * NCLS / 4];   // M3 x
__device__ float4 g_t2[NNODES * NCLS / 4];   // w + M2 x
__device__ float4 g_M4[3 * NCLS * D / 4];    // M1, M2, M3
__device__ float  g_v[2 * NCLS];             // v1, c
__device__ int    g_is64;                    // 1 if edge_index is int64
__device__ int2   g_edge[NEDGES];            // packed (src, dst)
__device__ int    g_srcs[NEDGES];            // src sorted by dst (CSR adj)
__device__ int    g_cnt[NNODES];             // per-dst counts (histogram)
__device__ int    g_cur[NNODES];             // reorder cursors
__device__ int    g_start[NNODES + 1];       // CSR row starts

// ---------------------------------------------------------------------------
// Fused: zero histogram + dtype detect + unified weight fold (one block).
// ---------------------------------------------------------------------------
__global__ __launch_bounds__(256) void dwfold_kernel(
        const unsigned int* __restrict__ widx,
        const float* __restrict__ W1r, const float* __restrict__ b1,
        const float* __restrict__ W1o, const float* __restrict__ W2r,
        const float* __restrict__ b2,  const float* __restrict__ W2o,
        const float* __restrict__ Wl,  const float* __restrict__ bl) {
    __shared__ float sWa[D * D];        // W2r then W1r
    __shared__ float sWb[D * D];        // W2o then W1o
    __shared__ float sWl[NCLS * D];
    __shared__ float sPr[NCLS * D];
    __shared__ float sPo[NCLS * D];
    __shared__ float sb1[D], sb2[D], sur[D], suo[D];
    __shared__ int any_nonzero;
    const int tid = threadIdx.x;

    // ---- zero histogram (int4 = 16B stores) ----
    for (int i = tid; i < NNODES / 4; i += 256)
        ((int4*)g_cnt)[i] = make_int4(0, 0, 0, 0);

    // ---- dtype detect ----
    if (tid == 0) any_nonzero = 0;
    __syncthreads();
    {
        unsigned int acc = 0;
        for (int i = tid; i < 4096; i += 256) acc |= widx[2 * i + 1];
        if (acc) any_nonzero = 1;
    }

    // ---- Phase 1 loads ----
    {
        const int nf4 = D * D / 4;
        for (int i = tid; i < nf4; i += 256) {
            ((float4*)sWa)[i] = ((const float4*)W2r)[i];
            ((float4*)sWb)[i] = ((const float4*)W2o)[i];
        }
        for (int i = tid; i < NCLS * D / 4; i += 256)
            ((float4*)sWl)[i] = ((const float4*)Wl)[i];
        if (tid < D / 4) {
            ((float4*)sb1)[tid] = ((const float4*)b1)[tid];
            ((float4*)sb2)[tid] = ((const float4*)b2)[tid];
        }
    }
    __syncthreads();
    if (tid == 0) g_is64 = any_nonzero ? 0 : 1;

    if (tid < D) {
        float s = 0.f;
        for (int k = 0; k < D; k++) s += sWa[tid * D + k] * sb1[k];
        sur[tid] = s;
    } else if (tid < 2 * D) {
        const int m = tid - D;
        float s = 0.f;
        for (int k = 0; k < D; k++) s += sWb[m * D + k] * sb1[k];
        suo[m] = s;
    }

    for (int idx = tid; idx < NCLS * D; idx += 256) {
        const int r = idx >> 6, m = idx & 63;
        float pr = 0.f, po = 0.f;
        for (int j = 0; j < D; j++) {
            const float w = sWl[r * D + j];
            pr += w * sWa[j * D + m];
            po += w * sWb[j * D + m];
        }
        sPr[idx] = pr;
        sPo[idx] = po;
    }
    __syncthreads();

    if (tid < NCLS) {
        float s = 0.f;
        for (int m = 0; m < D; m++) s += sWl[tid * D + m] * sur[m];
        g_v[tid] = s;
    } else if (tid < 2 * NCLS) {
        const int r = tid - NCLS;
        float s = 0.f;
        for (int m = 0; m < D; m++) s += sWl[r * D + m] * (suo[m] + sb2[m]);
        g_v[NCLS + r] = s + bl[r];
    }

    // ---- Phase 2 loads: W1r -> sWa, W1o -> sWb ----
    {
        const int nf4 = D * D / 4;
        for (int i = tid; i < nf4; i += 256) {
            ((float4*)sWa)[i] = ((const float4*)W1r)[i];
            ((float4*)sWb)[i] = ((const float4*)W1o)[i];
        }
    }
    __syncthreads();

    for (int idx = tid; idx < 3 * NCLS * D; idx += 256) {
        const int which = idx / (NCLS * D);
        const int rem = idx - which * (NCLS * D);
        const int r = rem >> 6, k = rem & 63;
        float s = 0.f;
        if (which == 0) {
            for (int m = 0; m < D; m++) s += sPr[r * D + m] * sWa[m * D + k];
        } else if (which == 1) {
            for (int m = 0; m < D; m++)
                s += sPr[r * D + m] * sWb[m * D + k] + sPo[r * D + m] * sWa[m * D + k];
        } else {
            for (int m = 0; m < D; m++) s += sPo[r * D + m] * sWb[m * D + k];
        }
        ((float*)g_M4)[idx] = s;
    }
}

// ---------------------------------------------------------------------------
// transform: t1/u2/u3 = M{1,2,3} x  (LDS.128, XOR-swizzled M tile)
//            + edge pack to int2 + dst histogram (exactly 1 edge per thread)
// ---------------------------------------------------------------------------
__global__ __launch_bounds__(256) void transform_kernel(
        const float* __restrict__ x, const void* __restrict__ eidx) {
    __shared__ float4 sM4[3 * NCLS * 16];  // 768 float4 = 12 KB (swizzled)
    __shared__ float4 sx4[16 * 16];        // 256 float4 = 4 KB
    const int tid = threadIdx.x;

    // Edge pack + histogram (this thread's edge)
    {
        const int e = blockIdx.x * 256 + tid;          // 3125*256 = 800000 exact
        int s, d;
        if (g_is64) {
            const long long* ei = (const long long*)eidx;
            s = (int)ei[e];
            d = (int)ei[NEDGES + e];
        } else {
            const int* ei = (const int*)eidx;
            s = ei[e];
            d = ei[NEDGES + e];
        }
        g_edge[e] = make_int2(s, d);
        atomicAdd(&g_cnt[d], 1);
    }

    // Load M with XOR swizzle: (row, k4) -> slot row*16 + (k4 ^ (row&15))
    for (int i = tid; i < 3 * NCLS * 16; i += 256) {
        const int row = i >> 4, k4 = i & 15;
        sM4[(row << 4) | (k4 ^ (row & 15))] = g_M4[i];
    }
    const int nodeBase = blockIdx.x * 16;
    sx4[tid] = ((const float4*)(x + (size_t)nodeBase * D))[tid];
    __syncthreads();

    const int j = tid >> 4;    // node within block
    const int r = tid & 15;    // class
    float a1 = 0.f, a2 = 0.f, a3 = 0.f;
    const float4* xb = &sx4[j << 4];
    #pragma unroll 4
    for (int k4 = 0; k4 < 16; k4++) {
        const float4 xv = xb[k4];
        const int sw = (r << 4) | (k4 ^ r);
        const float4 a = sM4[sw];
        const float4 b = sM4[256 + sw];
        const float4 c = sM4[512 + sw];
        a1 += a.x * xv.x + a.y * xv.y + a.z * xv.z + a.w * xv.w;
        a2 += b.x * xv.x + b.y * xv.y + b.z * xv.z + b.w * xv.w;
        a3 += c.x * xv.x + c.y * xv.y + c.z * xv.z + c.w * xv.w;
    }
    const int i = nodeBase + j;
    ((float*)g_t1)[i * NCLS + r] = a1;
    ((float*)g_u2)[i * NCLS + r] = a2;
    ((float*)g_u3)[i * NCLS + r] = a3;
}

// ---------------------------------------------------------------------------
// Exclusive scan of g_cnt -> g_start, g_cur.  One block, 1024 threads.
// ---------------------------------------------------------------------------
#define SCAN_PER 49   // ceil(50000/1024)

__global__ __launch_bounds__(1024) void scan_kernel() {
    __shared__ int part[1024];
    const int t = threadIdx.x;
    const int base = t * SCAN_PER;
    int sum = 0;
    for (int k = 0; k < SCAN_PER; k++) {
        const int i = base + k;
        if (i < NNODES) sum += g_cnt[i];
    }
    part[t] = sum;
    __syncthreads();
    // Inclusive Hillis-Steele scan over 1024 partials
    for (int off = 1; off < 1024; off <<= 1) {
        const int tmp = (t >= off) ? part[t - off] : 0;
        __syncthreads();
        part[t] += tmp;
        __syncthreads();
    }
    int run = part[t] - sum;   // exclusive prefix for this thread's range
    for (int k = 0; k < SCAN_PER; k++) {
        const int i = base + k;
        if (i < NNODES) {
            const int c = g_cnt[i];
            g_start[i] = run;
            g_cur[i] = run;
            run += c;
        }
    }
    if (t == 1023) g_start[NNODES] = run;   // = NEDGES
}

// ---------------------------------------------------------------------------
// Reorder: srcs grouped by dst (CSR adjacency).
// ---------------------------------------------------------------------------
__global__ __launch_bounds__(256) void reorder_kernel() {
    const int e = blockIdx.x * 256 + threadIdx.x;
    const int2 sd = g_edge[e];
    const int pos = atomicAdd(&g_cur[sd.y], 1);
    g_srcs[pos] = sd.x;
}

// ---------------------------------------------------------------------------
// agg0 (+fused combine): w = A t1 per node (gather, no atomics);
//   t2 = w + u2 ;  out = u3 + deg*v1 + c.
// 16 lanes per node: srcs read is broadcast, row gather is a 64B segment.
// ---------------------------------------------------------------------------
__global__ __launch_bounds__(256) void agg0_kernel(float* __restrict__ d_out) {
    __shared__ float sv[2 * NCLS];
    const int tid = threadIdx.x;
    if (tid < 2 * NCLS) sv[tid] = g_v[tid];
    __syncthreads();
    const int i = blockIdx.x * 16 + (tid >> 4);   // 3125*16 = 50000 exact
    const int r = tid & 15;
    const int st = g_start[i], en = g_start[i + 1];
    const float* t1 = (const float*)g_t1;
    float w = 0.f;
    for (int e = st; e < en; e++)
        w += t1[g_srcs[e] * NCLS + r];
    const int idx = i * NCLS + r;
    ((float*)g_t2)[idx] = w + ((const float*)g_u2)[idx];
    d_out[idx] = ((const float*)g_u3)[idx] + (float)(en - st) * sv[r] + sv[NCLS + r];
}

// ---------------------------------------------------------------------------
// agg1: out += A t2 per node (gather, coalesced RMW on out).
// ---------------------------------------------------------------------------
__global__ __launch_bounds__(256) void agg1_kernel(float* __restrict__ d_out) {
    const int tid = threadIdx.x;
    const int i = blockIdx.x * 16 + (tid >> 4);
    const int r = tid & 15;
    const int st = g_start[i], en = g_start[i + 1];
    const float* t2 = (const float*)g_t2;
    float w = 0.f;
    for (int e = st; e < en; e++)
        w += t2[g_srcs[e] * NCLS + r];
    const int idx = i * NCLS + r;
    d_out[idx] += w;
}

// ---------------------------------------------------------------------------
extern "C" void kernel_launch(void* const* d_in, const int* in_sizes, int n_in,
                              void* d_out, int out_size) {
    const float* x   = (const float*)d_in[0];
    const void*  eix = d_in[1];
    const float* W1r = (const float*)d_in[2];
    const float* b1  = (const float*)d_in[3];
    const float* W1o = (const float*)d_in[4];
    const float* W2r = (const float*)d_in[5];
    const float* b2  = (const float*)d_in[6];
    const float* W2o = (const float*)d_in[7];
    const float* Wl  = (const float*)d_in[8];
    const float* bl  = (const float*)d_in[9];
    float* out = (float*)d_out;

    // Zero hist + dtype detect + weight fold (one block)
    dwfold_kernel<<<1, 256>>>((const unsigned int*)eix, W1r, b1, W1o, W2r, b2, W2o, Wl, bl);

    // Projection + edge pack + dst histogram
    transform_kernel<<<3125, 256>>>(x, eix);

    // CSR build
    scan_kernel<<<1, 1024>>>();
    reorder_kernel<<<3125, 256>>>();

    // Gather aggregation, hop 1 (+combine fused)
    agg0_kernel<<<3125, 256>>>(out);

    // Gather aggregation, hop 2
    agg1_kernel<<<3125, 256>>>(out);
}

// round 9
// speedup vs baseline: 1.7084x; 1.7084x over previous
#include <cuda_runtime.h>
#include <cuda_bf16.h>

// Problem constants (fixed by the reference)
#define NNODES 50000
#define NEDGES 800000
#define D      64
#define NCLS   16

// Scratch (device globals)
__device__ float4 g_t1[NNODES * NCLS / 4];   // M1 x
__device__ float4 g_t2[NNODES * NCLS / 4];   // u2 + v1, then += A t1
__device__ float4 g_M4[3 * NCLS * D / 4];    // M1, M2, M3
__device__ float  g_v[2 * NCLS];             // v1, c
__device__ int    g_is64;                    // 1 if edge_index is int64
__device__ int4   g_edge4[NEDGES / 2];       // packed (s0,d0,s1,d1)

// ---------------------------------------------------------------------------
// Fused: dtype detect + unified weight fold (one block, smem-resident).
//   Phase 1: P_r = Wl*W2r, P_o = Wl*W2o; v1 = Wl*(W2r b1); c = Wl*(W2o b1+b2)+bl
//   Phase 2: M1 = P_r*W1r, M2 = P_r*W1o + P_o*W1r, M3 = P_o*W1o
// ---------------------------------------------------------------------------
__global__ __launch_bounds__(256) void dwfold_kernel(
        const unsigned int* __restrict__ widx,
        const float* __restrict__ W1r, const float* __restrict__ b1,
        const float* __restrict__ W1o, const float* __restrict__ W2r,
        const float* __restrict__ b2,  const float* __restrict__ W2o,
        const float* __restrict__ Wl,  const float* __restrict__ bl) {
    __shared__ float sWa[D * D];        // W2r then W1r
    __shared__ float sWb[D * D];        // W2o then W1o
    __shared__ float sWl[NCLS * D];
    __shared__ float sPr[NCLS * D];
    __shared__ float sPo[NCLS * D];
    __shared__ float sb1[D], sb2[D], sur[D], suo[D];
    __shared__ int any_nonzero;
    const int tid = threadIdx.x;

    // ---- dtype detect ----
    if (tid == 0) any_nonzero = 0;
    __syncthreads();
    {
        unsigned int acc = 0;
        for (int i = tid; i < 4096; i += 256) acc |= widx[2 * i + 1];
        if (acc) any_nonzero = 1;
    }

    // ---- Phase 1 loads ----
    {
        const int nf4 = D * D / 4;
        for (int i = tid; i < nf4; i += 256) {
            ((float4*)sWa)[i] = ((const float4*)W2r)[i];
            ((float4*)sWb)[i] = ((const float4*)W2o)[i];
        }
        for (int i = tid; i < NCLS * D / 4; i += 256)
            ((float4*)sWl)[i] = ((const float4*)Wl)[i];
        if (tid < D / 4) {
            ((float4*)sb1)[tid] = ((const float4*)b1)[tid];
            ((float4*)sb2)[tid] = ((const float4*)b2)[tid];
        }
    }
    __syncthreads();
    if (tid == 0) g_is64 = any_nonzero ? 0 : 1;

    if (tid < D) {
        float s = 0.f;
        for (int k = 0; k < D; k++) s += sWa[tid * D + k] * sb1[k];
        sur[tid] = s;
    } else if (tid < 2 * D) {
        const int m = tid - D;
        float s = 0.f;
        for (int k = 0; k < D; k++) s += sWb[m * D + k] * sb1[k];
        suo[m] = s;
    }

    for (int idx = tid; idx < NCLS * D; idx += 256) {
        const int r = idx >> 6, m = idx & 63;
        float pr = 0.f, po = 0.f;
        for (int j = 0; j < D; j++) {
            const float w = sWl[r * D + j];
            pr += w * sWa[j * D + m];
            po += w * sWb[j * D + m];
        }
        sPr[idx] = pr;
        sPo[idx] = po;
    }
    __syncthreads();

    if (tid < NCLS) {
        float s = 0.f;
        for (int m = 0; m < D; m++) s += sWl[tid * D + m] * sur[m];
        g_v[tid] = s;
    } else if (tid < 2 * NCLS) {
        const int r = tid - NCLS;
        float s = 0.f;
        for (int m = 0; m < D; m++) s += sWl[r * D + m] * (suo[m] + sb2[m]);
        g_v[NCLS + r] = s + bl[r];
    }

    // ---- Phase 2 loads: W1r -> sWa, W1o -> sWb ----
    {
        const int nf4 = D * D / 4;
        for (int i = tid; i < nf4; i += 256) {
            ((float4*)sWa)[i] = ((const float4*)W1r)[i];
            ((float4*)sWb)[i] = ((const float4*)W1o)[i];
        }
    }
    __syncthreads();

    for (int idx = tid; idx < 3 * NCLS * D; idx += 256) {
        const int which = idx / (NCLS * D);
        const int rem = idx - which * (NCLS * D);
        const int r = rem >> 6, k = rem & 63;
        float s = 0.f;
        if (which == 0) {
            for (int m = 0; m < D; m++) s += sPr[r * D + m] * sWa[m * D + k];
        } else if (which == 1) {
            for (int m = 0; m < D; m++)
                s += sPr[r * D + m] * sWb[m * D + k] + sPo[r * D + m] * sWa[m * D + k];
        } else {
            for (int m = 0; m < D; m++) s += sPo[r * D + m] * sWb[m * D + k];
        }
        ((float*)g_M4)[idx] = s;
    }
}

// ---------------------------------------------------------------------------
// transform: t1 = M1 x ; t2 = M2 x + v1 ; out = M3 x + c
// (v1 folded into t2 so A t2 generates the deg*v1 term; no degree counting)
// LDS.128 inner loop with XOR-swizzled M tile. 16 nodes / 256-thread block.
// ---------------------------------------------------------------------------
__global__ __launch_bounds__(256) void transform_kernel(
        const float* __restrict__ x, float* __restrict__ d_out) {
    __shared__ float4 sM4[3 * NCLS * 16];  // 768 float4 = 12 KB (swizzled)
    __shared__ float4 sx4[16 * 16];        // 256 float4 = 4 KB
    __shared__ float sv[2 * NCLS];
    const int tid = threadIdx.x;

    if (tid < 2 * NCLS) sv[tid] = g_v[tid];
    // Load M with XOR swizzle: (row, k4) -> slot row*16 + (k4 ^ (row&15))
    for (int i = tid; i < 3 * NCLS * 16; i += 256) {
        const int row = i >> 4, k4 = i & 15;
        sM4[(row << 4) | (k4 ^ (row & 15))] = g_M4[i];
    }
    const int nodeBase = blockIdx.x * 16;
    sx4[tid] = ((const float4*)(x + (size_t)nodeBase * D))[tid];
    __syncthreads();

    const int j = tid >> 4;    // node within block
    const int r = tid & 15;    // class
    float a1 = 0.f, a2 = 0.f, a3 = 0.f;
    const float4* xb = &sx4[j << 4];
    #pragma unroll 4
    for (int k4 = 0; k4 < 16; k4++) {
        const float4 xv = xb[k4];
        const int sw = (r << 4) | (k4 ^ r);
        const float4 a = sM4[sw];
        const float4 b = sM4[256 + sw];
        const float4 c = sM4[512 + sw];
        a1 += a.x * xv.x + a.y * xv.y + a.z * xv.z + a.w * xv.w;
        a2 += b.x * xv.x + b.y * xv.y + b.z * xv.z + b.w * xv.w;
        a3 += c.x * xv.x + c.y * xv.y + c.z * xv.z + c.w * xv.w;
    }
    const int idx = (nodeBase + j) * NCLS + r;
    ((float*)g_t1)[idx] = a1;
    ((float*)g_t2)[idx] = a2 + sv[r];          // u2 + v1
    d_out[idx] = a3 + sv[NCLS + r];            // u3 + c
}

// ---------------------------------------------------------------------------
// Scatter pass 0 (+edge packing): 2 edges/thread.
//   g_t2[dst] += t1[src]  (4 float4 REDs per edge)
// ---------------------------------------------------------------------------
__global__ __launch_bounds__(256) void scatter0_kernel(const void* __restrict__ eidx) {
    const int t = blockIdx.x * 256 + threadIdx.x;     // pair index
    if (t >= NEDGES / 2) return;
    int s0, d0, s1, d1;
    if (g_is64) {
        const longlong2 ss = ((const longlong2*)eidx)[t];
        const longlong2 dd = ((const longlong2*)((const long long*)eidx + NEDGES))[t];
        s0 = (int)ss.x; s1 = (int)ss.y;
        d0 = (int)dd.x; d1 = (int)dd.y;
    } else {
        const int2 ss = ((const int2*)eidx)[t];
        const int2 dd = ((const int2*)((const int*)eidx + NEDGES))[t];
        s0 = ss.x; s1 = ss.y;
        d0 = dd.x; d1 = dd.y;
    }
    g_edge4[t] = make_int4(s0, d0, s1, d1);
    // Issue both gathers before any RED (MLP=8 loads)
    const float4* va = &g_t1[s0 * (NCLS / 4)];
    const float4* vb = &g_t1[s1 * (NCLS / 4)];
    const float4 a0 = va[0], a1 = va[1], a2 = va[2], a3 = va[3];
    const float4 b0 = vb[0], b1 = vb[1], b2 = vb[2], b3 = vb[3];
    float4* oa = &g_t2[d0 * (NCLS / 4)];
    float4* ob = &g_t2[d1 * (NCLS / 4)];
    atomicAdd(oa + 0, a0); atomicAdd(oa + 1, a1);
    atomicAdd(oa + 2, a2); atomicAdd(oa + 3, a3);
    atomicAdd(ob + 0, b0); atomicAdd(ob + 1, b1);
    atomicAdd(ob + 2, b2); atomicAdd(ob + 3, b3);
}

// ---------------------------------------------------------------------------
// Scatter pass 1: out[dst] += t2[src], 2 edges/thread via packed g_edge4.
// ---------------------------------------------------------------------------
__global__ __launch_bounds__(256) void scatter1_kernel(float* __restrict__ d_out) {
    const int t = blockIdx.x * 256 + threadIdx.x;
    if (t >= NEDGES / 2) return;
    const int4 ed = g_edge4[t];                       // (s0,d0,s1,d1)
    const float4* va = &g_t2[ed.x * (NCLS / 4)];
    const float4* vb = &g_t2[ed.z * (NCLS / 4)];
    const float4 a0 = va[0], a1 = va[1], a2 = va[2], a3 = va[3];
    const float4 b0 = vb[0], b1 = vb[1], b2 = vb[2], b3 = vb[3];
    float4* oa = (float4*)(d_out + ed.y * NCLS);
    float4* ob = (float4*)(d_out + ed.w * NCLS);
    atomicAdd(oa + 0, a0); atomicAdd(oa + 1, a1);
    atomicAdd(oa + 2, a2); atomicAdd(oa + 3, a3);
    atomicAdd(ob + 0, b0); atomicAdd(ob + 1, b1);
    atomicAdd(ob + 2, b2); atomicAdd(ob + 3, b3);
}

// ---------------------------------------------------------------------------
extern "C" void kernel_launch(void* const* d_in, const int* in_sizes, int n_in,
                              void* d_out, int out_size) {
    const float* x   = (const float*)d_in[0];
    const void*  eix = d_in[1];
    const float* W1r = (const float*)d_in[2];
    const float* b1  = (const float*)d_in[3];
    const float* W1o = (const float*)d_in[4];
    const float* W2r = (const float*)d_in[5];
    const float* b2  = (const float*)d_in[6];
    const float* W2o = (const float*)d_in[7];
    const float* Wl  = (const float*)d_in[8];
    const float* bl  = (const float*)d_in[9];
    float* out = (float*)d_out;

    // dtype detect + weight fold (one block)
    dwfold_kernel<<<1, 256>>>((const unsigned int*)eix, W1r, b1, W1o, W2r, b2, W2o, Wl, bl);

    // t1 = M1 x ; t2 = M2 x + v1 ; out = M3 x + c
    transform_kernel<<<3125, 256>>>(x, out);

    // t2 += A t1  (+ pack edges)
    const int pairBlocks = (NEDGES / 2 + 255) / 256;  // 1563
    scatter0_kernel<<<pairBlocks, 256>>>(eix);

    // out += A t2
    scatter1_kernel<<<pairBlocks, 256>>>(out);
}

// round 10
// speedup vs baseline: 2.1830x; 1.2778x over previous
#include <cuda_runtime.h>
#include <cuda_bf16.h>

// Problem constants (fixed by the reference)
#define NNODES 50000
#define NEDGES 800000
#define D      64
#define NCLS   16

// Scratch (device globals)
__device__ float4 g_t1[NNODES * NCLS / 4];   // M1 x
__device__ float4 g_t2[NNODES * NCLS / 4];   // u2 + v1, then += A t1
__device__ float4 g_M4[3 * NCLS * D / 4];    // M1, M2, M3
__device__ float  g_v[2 * NCLS];             // v1, c
__device__ int    g_is64;                    // 1 if edge_index is int64
__device__ int2   g_edge2[NEDGES];           // packed (src, dst)

// ---------------------------------------------------------------------------
// Fused: dtype detect + unified weight fold (one block, smem-resident).
//   Phase 1: P_r = Wl*W2r, P_o = Wl*W2o; v1 = Wl*(W2r b1); c = Wl*(W2o b1+b2)+bl
//   Phase 2: M1 = P_r*W1r, M2 = P_r*W1o + P_o*W1r, M3 = P_o*W1o
// ---------------------------------------------------------------------------
__global__ __launch_bounds__(256) void dwfold_kernel(
        const unsigned int* __restrict__ widx,
        const float* __restrict__ W1r, const float* __restrict__ b1,
        const float* __restrict__ W1o, const float* __restrict__ W2r,
        const float* __restrict__ b2,  const float* __restrict__ W2o,
        const float* __restrict__ Wl,  const float* __restrict__ bl) {
    __shared__ float sWa[D * D];        // W2r then W1r
    __shared__ float sWb[D * D];        // W2o then W1o
    __shared__ float sWl[NCLS * D];
    __shared__ float sPr[NCLS * D];
    __shared__ float sPo[NCLS * D];
    __shared__ float sb1[D], sb2[D], sur[D], suo[D];
    __shared__ int any_nonzero;
    const int tid = threadIdx.x;

    // ---- dtype detect ----
    if (tid == 0) any_nonzero = 0;
    __syncthreads();
    {
        unsigned int acc = 0;
        for (int i = tid; i < 4096; i += 256) acc |= widx[2 * i + 1];
        if (acc) any_nonzero = 1;
    }

    // ---- Phase 1 loads ----
    {
        const int nf4 = D * D / 4;
        for (int i = tid; i < nf4; i += 256) {
            ((float4*)sWa)[i] = ((const float4*)W2r)[i];
            ((float4*)sWb)[i] = ((const float4*)W2o)[i];
        }
        for (int i = tid; i < NCLS * D / 4; i += 256)
            ((float4*)sWl)[i] = ((const float4*)Wl)[i];
        if (tid < D / 4) {
            ((float4*)sb1)[tid] = ((const float4*)b1)[tid];
            ((float4*)sb2)[tid] = ((const float4*)b2)[tid];
        }
    }
    __syncthreads();
    if (tid == 0) g_is64 = any_nonzero ? 0 : 1;

    if (tid < D) {
        float s = 0.f;
        for (int k = 0; k < D; k++) s += sWa[tid * D + k] * sb1[k];
        sur[tid] = s;
    } else if (tid < 2 * D) {
        const int m = tid - D;
        float s = 0.f;
        for (int k = 0; k < D; k++) s += sWb[m * D + k] * sb1[k];
        suo[m] = s;
    }

    for (int idx = tid; idx < NCLS * D; idx += 256) {
        const int r = idx >> 6, m = idx & 63;
        float pr = 0.f, po = 0.f;
        for (int j = 0; j < D; j++) {
            const float w = sWl[r * D + j];
            pr += w * sWa[j * D + m];
            po += w * sWb[j * D + m];
        }
        sPr[idx] = pr;
        sPo[idx] = po;
    }
    __syncthreads();

    if (tid < NCLS) {
        float s = 0.f;
        for (int m = 0; m < D; m++) s += sWl[tid * D + m] * sur[m];
        g_v[tid] = s;
    } else if (tid < 2 * NCLS) {
        const int r = tid - NCLS;
        float s = 0.f;
        for (int m = 0; m < D; m++) s += sWl[r * D + m] * (suo[m] + sb2[m]);
        g_v[NCLS + r] = s + bl[r];
    }

    // ---- Phase 2 loads: W1r -> sWa, W1o -> sWb ----
    {
        const int nf4 = D * D / 4;
        for (int i = tid; i < nf4; i += 256) {
            ((float4*)sWa)[i] = ((const float4*)W1r)[i];
            ((float4*)sWb)[i] = ((const float4*)W1o)[i];
        }
    }
    __syncthreads();

    for (int idx = tid; idx < 3 * NCLS * D; idx += 256) {
        const int which = idx / (NCLS * D);
        const int rem = idx - which * (NCLS * D);
        const int r = rem >> 6, k = rem & 63;
        float s = 0.f;
        if (which == 0) {
            for (int m = 0; m < D; m++) s += sPr[r * D + m] * sWa[m * D + k];
        } else if (which == 1) {
            for (int m = 0; m < D; m++)
                s += sPr[r * D + m] * sWb[m * D + k] + sPo[r * D + m] * sWa[m * D + k];
        } else {
            for (int m = 0; m < D; m++) s += sPo[r * D + m] * sWb[m * D + k];
        }
        ((float*)g_M4)[idx] = s;
    }
}

// ---------------------------------------------------------------------------
// transform: t1 = M1 x ; t2 = M2 x + v1 ; out = M3 x + c
// (v1 folded into t2 so A t2 generates the deg*v1 term)
// LDS.128 inner loop with XOR-swizzled M tile. 16 nodes / 256-thread block.
// ---------------------------------------------------------------------------
__global__ __launch_bounds__(256) void transform_kernel(
        const float* __restrict__ x, float* __restrict__ d_out) {
    __shared__ float4 sM4[3 * NCLS * 16];  // 768 float4 = 12 KB (swizzled)
    __shared__ float4 sx4[16 * 16];        // 256 float4 = 4 KB
    __shared__ float sv[2 * NCLS];
    const int tid = threadIdx.x;

    if (tid < 2 * NCLS) sv[tid] = g_v[tid];
    for (int i = tid; i < 3 * NCLS * 16; i += 256) {
        const int row = i >> 4, k4 = i & 15;
        sM4[(row << 4) | (k4 ^ (row & 15))] = g_M4[i];
    }
    const int nodeBase = blockIdx.x * 16;
    sx4[tid] = ((const float4*)(x + (size_t)nodeBase * D))[tid];
    __syncthreads();

    const int j = tid >> 4;    // node within block
    const int r = tid & 15;    // class
    float a1 = 0.f, a2 = 0.f, a3 = 0.f;
    const float4* xb = &sx4[j << 4];
    #pragma unroll 4
    for (int k4 = 0; k4 < 16; k4++) {
        const float4 xv = xb[k4];
        const int sw = (r << 4) | (k4 ^ r);
        const float4 a = sM4[sw];
        const float4 b = sM4[256 + sw];
        const float4 c = sM4[512 + sw];
        a1 += a.x * xv.x + a.y * xv.y + a.z * xv.z + a.w * xv.w;
        a2 += b.x * xv.x + b.y * xv.y + b.z * xv.z + b.w * xv.w;
        a3 += c.x * xv.x + c.y * xv.y + c.z * xv.z + c.w * xv.w;
    }
    const int idx = (nodeBase + j) * NCLS + r;
    ((float*)g_t1)[idx] = a1;
    ((float*)g_t2)[idx] = a2 + sv[r];          // u2 + v1
    d_out[idx] = a3 + sv[NCLS + r];            // u3 + c
}

// ---------------------------------------------------------------------------
// Scatter pass 0 (+edge packing), 4 lanes per edge:
//   lane c of edge e gathers t1[s*4+c] and REDs into t2[d*4+c].
// Minimal per-thread state -> max occupancy / outstanding loads.
// ---------------------------------------------------------------------------
__global__ __launch_bounds__(256) void scatter0_kernel(const void* __restrict__ eidx) {
    const int t = blockIdx.x * 256 + threadIdx.x;   // grid exact: 12500*256 = 3.2M
    const int e = t >> 2;                           // edge
    const int c = t & 3;                            // float4 component
    int s, d;
    if (g_is64) {
        const long long* ei = (const long long*)eidx;
        s = (int)ei[e];
        d = (int)ei[NEDGES + e];
    } else {
        const int* ei = (const int*)eidx;
        s = ei[e];
        d = ei[NEDGES + e];
    }
    if (c == 0) g_edge2[e] = make_int2(s, d);
    const float4 v = g_t1[s * 4 + c];
    atomicAdd(&g_t2[d * 4 + c], v);
}

// ---------------------------------------------------------------------------
// Scatter pass 1: out[dst] += t2[src], 4 lanes per edge via packed g_edge2.
// ---------------------------------------------------------------------------
__global__ __launch_bounds__(256) void scatter1_kernel(float* __restrict__ d_out) {
    const int t = blockIdx.x * 256 + threadIdx.x;
    const int e = t >> 2;
    const int c = t & 3;
    const int2 sd = g_edge2[e];                     // broadcast across 4 lanes
    const float4 v = g_t2[sd.x * 4 + c];
    atomicAdd((float4*)(d_out + sd.y * NCLS) + c, v);
}

// ---------------------------------------------------------------------------
extern "C" void kernel_launch(void* const* d_in, const int* in_sizes, int n_in,
                              void* d_out, int out_size) {
    const float* x   = (const float*)d_in[0];
    const void*  eix = d_in[1];
    const float* W1r = (const float*)d_in[2];
    const float* b1  = (const float*)d_in[3];
    const float* W1o = (const float*)d_in[4];
    const float* W2r = (const float*)d_in[5];
    const float* b2  = (const float*)d_in[6];
    const float* W2o = (const float*)d_in[7];
    const float* Wl  = (const float*)d_in[8];
    const float* bl  = (const float*)d_in[9];
    float* out = (float*)d_out;

    // dtype detect + weight fold (one block)
    dwfold_kernel<<<1, 256>>>((const unsigned int*)eix, W1r, b1, W1o, W2r, b2, W2o, Wl, bl);

    // t1 = M1 x ; t2 = M2 x + v1 ; out = M3 x + c
    transform_kernel<<<3125, 256>>>(x, out);

    // t2 += A t1  (+ pack edges);  4 lanes/edge
    const int laneBlocks = NEDGES * 4 / 256;        // 12500
    scatter0_kernel<<<laneBlocks, 256>>>(eix);

    // out += A t2
    scatter1_kernel<<<laneBlocks, 256>>>(out);
}

// round 11
// speedup vs baseline: 2.2171x; 1.0156x over previous
#include <cuda_runtime.h>
#include <cuda_bf16.h>

// Problem constants (fixed by the reference)
#define NNODES 50000
#define NEDGES 800000
#define D      64
#define NCLS   16

// Scratch (device globals)
__device__ float4 g_t1[NNODES * NCLS / 4];   // M1 x
__device__ float4 g_t2[NNODES * NCLS / 4];   // u2 + v1, then += A t1
__device__ float4 g_M4[3 * NCLS * D / 4];    // M1, M2, M3
__device__ float  g_v[2 * NCLS];             // v1, c
__device__ int    g_is64;                    // 1 if edge_index is int64
__device__ int2   g_edge2[NEDGES];           // packed (src, dst)

// ---------------------------------------------------------------------------
// Fused: dtype detect + unified weight fold (one block, smem-resident).
//   Phase 1: P_r = Wl*W2r, P_o = Wl*W2o; v1 = Wl*(W2r b1); c = Wl*(W2o b1+b2)+bl
//   Phase 2: M1 = P_r*W1r, M2 = P_r*W1o + P_o*W1r, M3 = P_o*W1o
// ---------------------------------------------------------------------------
__global__ __launch_bounds__(256) void dwfold_kernel(
        const unsigned int* __restrict__ widx,
        const float* __restrict__ W1r, const float* __restrict__ b1,
        const float* __restrict__ W1o, const float* __restrict__ W2r,
        const float* __restrict__ b2,  const float* __restrict__ W2o,
        const float* __restrict__ Wl,  const float* __restrict__ bl) {
    __shared__ float sWa[D * D];        // W2r then W1r
    __shared__ float sWb[D * D];        // W2o then W1o
    __shared__ float sWl[NCLS * D];
    __shared__ float sPr[NCLS * D];
    __shared__ float sPo[NCLS * D];
    __shared__ float sb1[D], sb2[D], sur[D], suo[D];
    __shared__ int any_nonzero;
    const int tid = threadIdx.x;

    // ---- dtype detect ----
    if (tid == 0) any_nonzero = 0;
    __syncthreads();
    {
        unsigned int acc = 0;
        for (int i = tid; i < 4096; i += 256) acc |= widx[2 * i + 1];
        if (acc) any_nonzero = 1;
    }

    // ---- Phase 1 loads ----
    {
        const int nf4 = D * D / 4;
        for (int i = tid; i < nf4; i += 256) {
            ((float4*)sWa)[i] = ((const float4*)W2r)[i];
            ((float4*)sWb)[i] = ((const float4*)W2o)[i];
        }
        for (int i = tid; i < NCLS * D / 4; i += 256)
            ((float4*)sWl)[i] = ((const float4*)Wl)[i];
        if (tid < D / 4) {
            ((float4*)sb1)[tid] = ((const float4*)b1)[tid];
            ((float4*)sb2)[tid] = ((const float4*)b2)[tid];
        }
    }
    __syncthreads();
    if (tid == 0) g_is64 = any_nonzero ? 0 : 1;

    if (tid < D) {
        float s = 0.f;
        for (int k = 0; k < D; k++) s += sWa[tid * D + k] * sb1[k];
        sur[tid] = s;
    } else if (tid < 2 * D) {
        const int m = tid - D;
        float s = 0.f;
        for (int k = 0; k < D; k++) s += sWb[m * D + k] * sb1[k];
        suo[m] = s;
    }

    for (int idx = tid; idx < NCLS * D; idx += 256) {
        const int r = idx >> 6, m = idx & 63;
        float pr = 0.f, po = 0.f;
        for (int j = 0; j < D; j++) {
            const float w = sWl[r * D + j];
            pr += w * sWa[j * D + m];
            po += w * sWb[j * D + m];
        }
        sPr[idx] = pr;
        sPo[idx] = po;
    }
    __syncthreads();

    if (tid < NCLS) {
        float s = 0.f;
        for (int m = 0; m < D; m++) s += sWl[tid * D + m] * sur[m];
        g_v[tid] = s;
    } else if (tid < 2 * NCLS) {
        const int r = tid - NCLS;
        float s = 0.f;
        for (int m = 0; m < D; m++) s += sWl[r * D + m] * (suo[m] + sb2[m]);
        g_v[NCLS + r] = s + bl[r];
    }

    // ---- Phase 2 loads: W1r -> sWa, W1o -> sWb ----
    {
        const int nf4 = D * D / 4;
        for (int i = tid; i < nf4; i += 256) {
            ((float4*)sWa)[i] = ((const float4*)W1r)[i];
            ((float4*)sWb)[i] = ((const float4*)W1o)[i];
        }
    }
    __syncthreads();

    for (int idx = tid; idx < 3 * NCLS * D; idx += 256) {
        const int which = idx / (NCLS * D);
        const int rem = idx - which * (NCLS * D);
        const int r = rem >> 6, k = rem & 63;
        float s = 0.f;
        if (which == 0) {
            for (int m = 0; m < D; m++) s += sPr[r * D + m] * sWa[m * D + k];
        } else if (which == 1) {
            for (int m = 0; m < D; m++)
                s += sPr[r * D + m] * sWb[m * D + k] + sPo[r * D + m] * sWa[m * D + k];
        } else {
            for (int m = 0; m < D; m++) s += sPo[r * D + m] * sWb[m * D + k];
        }
        ((float*)g_M4)[idx] = s;
    }
}

// ---------------------------------------------------------------------------
// transform: t1 = M1 x ; t2 = M2 x + v1 ; out = M3 x + c
//            + edge packing (1 edge per thread, hidden under the FMAs)
// LDS.128 inner loop with XOR-swizzled M tile. 16 nodes / 256-thread block.
// ---------------------------------------------------------------------------
__global__ __launch_bounds__(256) void transform_kernel(
        const float* __restrict__ x, const void* __restrict__ eidx,
        float* __restrict__ d_out) {
    __shared__ float4 sM4[3 * NCLS * 16];  // 768 float4 = 12 KB (swizzled)
    __shared__ float4 sx4[16 * 16];        // 256 float4 = 4 KB
    __shared__ float sv[2 * NCLS];
    const int tid = threadIdx.x;

    // Edge pack: issue index loads early; they drain under the matvec below.
    const int e = blockIdx.x * 256 + tid;          // 3125*256 = 800000 exact
    int es, ed;
    if (g_is64) {
        const long long* ei = (const long long*)eidx;
        es = (int)ei[e];
        ed = (int)ei[NEDGES + e];
    } else {
        const int* ei = (const int*)eidx;
        es = ei[e];
        ed = ei[NEDGES + e];
    }

    if (tid < 2 * NCLS) sv[tid] = g_v[tid];
    for (int i = tid; i < 3 * NCLS * 16; i += 256) {
        const int row = i >> 4, k4 = i & 15;
        sM4[(row << 4) | (k4 ^ (row & 15))] = g_M4[i];
    }
    const int nodeBase = blockIdx.x * 16;
    sx4[tid] = ((const float4*)(x + (size_t)nodeBase * D))[tid];
    __syncthreads();

    const int j = tid >> 4;    // node within block
    const int r = tid & 15;    // class
    float a1 = 0.f, a2 = 0.f, a3 = 0.f;
    const float4* xb = &sx4[j << 4];
    #pragma unroll 4
    for (int k4 = 0; k4 < 16; k4++) {
        const float4 xv = xb[k4];
        const int sw = (r << 4) | (k4 ^ r);
        const float4 a = sM4[sw];
        const float4 b = sM4[256 + sw];
        const float4 c = sM4[512 + sw];
        a1 += a.x * xv.x + a.y * xv.y + a.z * xv.z + a.w * xv.w;
        a2 += b.x * xv.x + b.y * xv.y + b.z * xv.z + b.w * xv.w;
        a3 += c.x * xv.x + c.y * xv.y + c.z * xv.z + c.w * xv.w;
    }
    const int idx = (nodeBase + j) * NCLS + r;
    ((float*)g_t1)[idx] = a1;
    ((float*)g_t2)[idx] = a2 + sv[r];          // u2 + v1
    d_out[idx] = a3 + sv[NCLS + r];            // u3 + c
    g_edge2[e] = make_int2(es, ed);
}

// ---------------------------------------------------------------------------
// Scatter: 4 lanes per edge, 2 edges per thread (e and e + E/2).
//   PASS 0: g_t2[dst] += t1[src]      PASS 1: out[dst] += t2[src]
// ---------------------------------------------------------------------------
template <int PASS>
__global__ __launch_bounds__(256) void scatter_kernel(float* __restrict__ d_out) {
    const int t = blockIdx.x * 256 + threadIdx.x;   // 6250*256 = 1.6M exact
    const int e0 = t >> 2;                          // first edge
    const int c = t & 3;                            // float4 component
    const int e1 = e0 + NEDGES / 2;                 // second edge
    const int2 sd0 = g_edge2[e0];
    const int2 sd1 = g_edge2[e1];
    const float4* srcArr = (PASS == 0) ? g_t1 : g_t2;
    const float4 v0 = srcArr[sd0.x * 4 + c];
    const float4 v1 = srcArr[sd1.x * 4 + c];
    if (PASS == 0) {
        atomicAdd(&g_t2[sd0.y * 4 + c], v0);
        atomicAdd(&g_t2[sd1.y * 4 + c], v1);
    } else {
        atomicAdd((float4*)(d_out + sd0.y * NCLS) + c, v0);
        atomicAdd((float4*)(d_out + sd1.y * NCLS) + c, v1);
    }
}

// ---------------------------------------------------------------------------
extern "C" void kernel_launch(void* const* d_in, const int* in_sizes, int n_in,
                              void* d_out, int out_size) {
    const float* x   = (const float*)d_in[0];
    const void*  eix = d_in[1];
    const float* W1r = (const float*)d_in[2];
    const float* b1  = (const float*)d_in[3];
    const float* W1o = (const float*)d_in[4];
    const float* W2r = (const float*)d_in[5];
    const float* b2  = (const float*)d_in[6];
    const float* W2o = (const float*)d_in[7];
    const float* Wl  = (const float*)d_in[8];
    const float* bl  = (const float*)d_in[9];
    float* out = (float*)d_out;

    // dtype detect + weight fold (one block)
    dwfold_kernel<<<1, 256>>>((const unsigned int*)eix, W1r, b1, W1o, W2r, b2, W2o, Wl, bl);

    // t1 = M1 x ; t2 = M2 x + v1 ; out = M3 x + c ; pack edges
    transform_kernel<<<3125, 256>>>(x, eix, out);

    // t2 += A t1 ; out += A t2   (4 lanes/edge, 2 edges/thread)
    const int scBlocks = NEDGES * 2 / 256;          // 6250
    scatter_kernel<0><<<scBlocks, 256>>>(out);
    scatter_kernel<1><<<scBlocks, 256>>>(out);
}

// round 12
// speedup vs baseline: 2.2180x; 1.0004x over previous
#include <cuda_runtime.h>
#include <cuda_bf16.h>

// Problem constants (fixed by the reference)
#define NNODES 50000
#define NEDGES 800000
#define D      64
#define NCLS   16

// Scratch (device globals)
__device__ float4 g_t1[NNODES * NCLS / 4];   // M1 x
__device__ float4 g_t2[NNODES * NCLS / 4];   // u2 + v1, then += A t1
__device__ float4 g_M4[3 * NCLS * D / 4];    // M1, M2, M3
__device__ float  g_v[2 * NCLS];             // v1, c
__device__ int    g_is64;                    // 1 if edge_index is int64
__device__ int2   g_edge2[NEDGES];           // packed (src, dst)

// ---------------------------------------------------------------------------
// Fused: dtype detect + unified weight fold (one block, smem-resident).
// ---------------------------------------------------------------------------
__global__ __launch_bounds__(256) void dwfold_kernel(
        const unsigned int* __restrict__ widx,
        const float* __restrict__ W1r, const float* __restrict__ b1,
        const float* __restrict__ W1o, const float* __restrict__ W2r,
        const float* __restrict__ b2,  const float* __restrict__ W2o,
        const float* __restrict__ Wl,  const float* __restrict__ bl) {
    __shared__ float sWa[D * D];        // W2r then W1r
    __shared__ float sWb[D * D];        // W2o then W1o
    __shared__ float sWl[NCLS * D];
    __shared__ float sPr[NCLS * D];
    __shared__ float sPo[NCLS * D];
    __shared__ float sb1[D], sb2[D], sur[D], suo[D];
    __shared__ int any_nonzero;
    const int tid = threadIdx.x;

    // ---- dtype detect ----
    if (tid == 0) any_nonzero = 0;
    __syncthreads();
    {
        unsigned int acc = 0;
        for (int i = tid; i < 4096; i += 256) acc |= widx[2 * i + 1];
        if (acc) any_nonzero = 1;
    }

    // ---- Phase 1 loads ----
    {
        const int nf4 = D * D / 4;
        for (int i = tid; i < nf4; i += 256) {
            ((float4*)sWa)[i] = ((const float4*)W2r)[i];
            ((float4*)sWb)[i] = ((const float4*)W2o)[i];
        }
        for (int i = tid; i < NCLS * D / 4; i += 256)
            ((float4*)sWl)[i] = ((const float4*)Wl)[i];
        if (tid < D / 4) {
            ((float4*)sb1)[tid] = ((const float4*)b1)[tid];
            ((float4*)sb2)[tid] = ((const float4*)b2)[tid];
        }
    }
    __syncthreads();
    if (tid == 0) g_is64 = any_nonzero ? 0 : 1;

    if (tid < D) {
        float s = 0.f;
        for (int k = 0; k < D; k++) s += sWa[tid * D + k] * sb1[k];
        sur[tid] = s;
    } else if (tid < 2 * D) {
        const int m = tid - D;
        float s = 0.f;
        for (int k = 0; k < D; k++) s += sWb[m * D + k] * sb1[k];
        suo[m] = s;
    }

    for (int idx = tid; idx < NCLS * D; idx += 256) {
        const int r = idx >> 6, m = idx & 63;
        float pr = 0.f, po = 0.f;
        for (int j = 0; j < D; j++) {
            const float w = sWl[r * D + j];
            pr += w * sWa[j * D + m];
            po += w * sWb[j * D + m];
        }
        sPr[idx] = pr;
        sPo[idx] = po;
    }
    __syncthreads();

    if (tid < NCLS) {
        float s = 0.f;
        for (int m = 0; m < D; m++) s += sWl[tid * D + m] * sur[m];
        g_v[tid] = s;
    } else if (tid < 2 * NCLS) {
        const int r = tid - NCLS;
        float s = 0.f;
        for (int m = 0; m < D; m++) s += sWl[r * D + m] * (suo[m] + sb2[m]);
        g_v[NCLS + r] = s + bl[r];
    }

    // ---- Phase 2 loads: W1r -> sWa, W1o -> sWb ----
    {
        const int nf4 = D * D / 4;
        for (int i = tid; i < nf4; i += 256) {
            ((float4*)sWa)[i] = ((const float4*)W1r)[i];
            ((float4*)sWb)[i] = ((const float4*)W1o)[i];
        }
    }
    __syncthreads();

    for (int idx = tid; idx < 3 * NCLS * D; idx += 256) {
        const int which = idx / (NCLS * D);
        const int rem = idx - which * (NCLS * D);
        const int r = rem >> 6, k = rem & 63;
        float s = 0.f;
        if (which == 0) {
            for (int m = 0; m < D; m++) s += sPr[r * D + m] * sWa[m * D + k];
        } else if (which == 1) {
            for (int m = 0; m < D; m++)
                s += sPr[r * D + m] * sWb[m * D + k] + sPo[r * D + m] * sWa[m * D + k];
        } else {
            for (int m = 0; m < D; m++) s += sPo[r * D + m] * sWb[m * D + k];
        }
        ((float*)g_M4)[idx] = s;
    }
}

// ---------------------------------------------------------------------------
// transform: t1 = M1 x ; t2 = M2 x + v1 ; out = M3 x + c ; edge packing.
// Inner loop uses packed fma.rn.f32x2 (Blackwell): float4 halves are adjacent
// register pairs, so the b64 packs should alias without extra MOVs.
// ---------------------------------------------------------------------------
__global__ __launch_bounds__(256) void transform_kernel(
        const float* __restrict__ x, const void* __restrict__ eidx,
        float* __restrict__ d_out) {
    __shared__ float4 sM4[3 * NCLS * 16];  // 768 float4 = 12 KB (swizzled)
    __shared__ float4 sx4[16 * 16];        // 256 float4 = 4 KB
    __shared__ float sv[2 * NCLS];
    const int tid = threadIdx.x;

    // Edge pack: issue index loads early; drains under the matvec below.
    const int e = blockIdx.x * 256 + tid;          // 3125*256 = 800000 exact
    int es, ed;
    if (g_is64) {
        const long long* ei = (const long long*)eidx;
        es = (int)ei[e];
        ed = (int)ei[NEDGES + e];
    } else {
        const int* ei = (const int*)eidx;
        es = ei[e];
        ed = ei[NEDGES + e];
    }

    if (tid < 2 * NCLS) sv[tid] = g_v[tid];
    for (int i = tid; i < 3 * NCLS * 16; i += 256) {
        const int row = i >> 4, k4 = i & 15;
        sM4[(row << 4) | (k4 ^ (row & 15))] = g_M4[i];
    }
    const int nodeBase = blockIdx.x * 16;
    sx4[tid] = ((const float4*)(x + (size_t)nodeBase * D))[tid];
    __syncthreads();

    const int j = tid >> 4;    // node within block
    const int r = tid & 15;    // class
    unsigned long long acc1 = 0ull, acc2 = 0ull, acc3 = 0ull;  // packed f32x2
    const float4* xb = &sx4[j << 4];
    #pragma unroll 4
    for (int k4 = 0; k4 < 16; k4++) {
        const float4 xv = xb[k4];
        const int sw = (r << 4) | (k4 ^ r);
        const float4 a = sM4[sw];
        const float4 b = sM4[256 + sw];
        const float4 c = sM4[512 + sw];
        unsigned long long xlo, xhi, t;
        asm("mov.b64 %0, {%1,%2};" : "=l"(xlo) : "f"(xv.x), "f"(xv.y));
        asm("mov.b64 %0, {%1,%2};" : "=l"(xhi) : "f"(xv.z), "f"(xv.w));
        asm("mov.b64 %0, {%1,%2};" : "=l"(t) : "f"(a.x), "f"(a.y));
        asm("fma.rn.f32x2 %0, %1, %2, %0;" : "+l"(acc1) : "l"(t), "l"(xlo));
        asm("mov.b64 %0, {%1,%2};" : "=l"(t) : "f"(a.z), "f"(a.w));
        asm("fma.rn.f32x2 %0, %1, %2, %0;" : "+l"(acc1) : "l"(t), "l"(xhi));
        asm("mov.b64 %0, {%1,%2};" : "=l"(t) : "f"(b.x), "f"(b.y));
        asm("fma.rn.f32x2 %0, %1, %2, %0;" : "+l"(acc2) : "l"(t), "l"(xlo));
        asm("mov.b64 %0, {%1,%2};" : "=l"(t) : "f"(b.z), "f"(b.w));
        asm("fma.rn.f32x2 %0, %1, %2, %0;" : "+l"(acc2) : "l"(t), "l"(xhi));
        asm("mov.b64 %0, {%1,%2};" : "=l"(t) : "f"(c.x), "f"(c.y));
        asm("fma.rn.f32x2 %0, %1, %2, %0;" : "+l"(acc3) : "l"(t), "l"(xlo));
        asm("mov.b64 %0, {%1,%2};" : "=l"(t) : "f"(c.z), "f"(c.w));
        asm("fma.rn.f32x2 %0, %1, %2, %0;" : "+l"(acc3) : "l"(t), "l"(xhi));
    }
    float a1lo, a1hi, a2lo, a2hi, a3lo, a3hi;
    asm("mov.b64 {%0,%1}, %2;" : "=f"(a1lo), "=f"(a1hi) : "l"(acc1));
    asm("mov.b64 {%0,%1}, %2;" : "=f"(a2lo), "=f"(a2hi) : "l"(acc2));
    asm("mov.b64 {%0,%1}, %2;" : "=f"(a3lo), "=f"(a3hi) : "l"(acc3));
    const int idx = (nodeBase + j) * NCLS + r;
    ((float*)g_t1)[idx] = a1lo + a1hi;
    ((float*)g_t2)[idx] = a2lo + a2hi + sv[r];           // u2 + v1
    d_out[idx] = a3lo + a3hi + sv[NCLS + r];             // u3 + c
    g_edge2[e] = make_int2(es, ed);
}

// ---------------------------------------------------------------------------
// Scatter: 4 lanes per edge, 4 edges per thread (g, g+E/4, g+E/2, g+3E/4).
//   PASS 0: g_t2[dst] += t1[src]      PASS 1: out[dst] += t2[src]
// ---------------------------------------------------------------------------
template <int PASS>
__global__ __launch_bounds__(256) void scatter_kernel(float* __restrict__ d_out) {
    const int t = blockIdx.x * 256 + threadIdx.x;   // 3125*256 = 800000 exact
    const int g = t >> 2;                           // edge group (200000)
    const int c = t & 3;                            // float4 component
    const int2 sd0 = g_edge2[g];
    const int2 sd1 = g_edge2[g + NEDGES / 4];
    const int2 sd2 = g_edge2[g + NEDGES / 2];
    const int2 sd3 = g_edge2[g + 3 * (NEDGES / 4)];
    const float4* srcArr = (PASS == 0) ? g_t1 : g_t2;
    const float4 v0 = srcArr[sd0.x * 4 + c];
    const float4 v1 = srcArr[sd1.x * 4 + c];
    const float4 v2 = srcArr[sd2.x * 4 + c];
    const float4 v3 = srcArr[sd3.x * 4 + c];
    if (PASS == 0) {
        atomicAdd(&g_t2[sd0.y * 4 + c], v0);
        atomicAdd(&g_t2[sd1.y * 4 + c], v1);
        atomicAdd(&g_t2[sd2.y * 4 + c], v2);
        atomicAdd(&g_t2[sd3.y * 4 + c], v3);
    } else {
        atomicAdd((float4*)(d_out + sd0.y * NCLS) + c, v0);
        atomicAdd((float4*)(d_out + sd1.y * NCLS) + c, v1);
        atomicAdd((float4*)(d_out + sd2.y * NCLS) + c, v2);
        atomicAdd((float4*)(d_out + sd3.y * NCLS) + c, v3);
    }
}

// ---------------------------------------------------------------------------
extern "C" void kernel_launch(void* const* d_in, const int* in_sizes, int n_in,
                              void* d_out, int out_size) {
    const float* x   = (const float*)d_in[0];
    const void*  eix = d_in[1];
    const float* W1r = (const float*)d_in[2];
    const float* b1  = (const float*)d_in[3];
    const float* W1o = (const float*)d_in[4];
    const float* W2r = (const float*)d_in[5];
    const float* b2  = (const float*)d_in[6];
    const float* W2o = (const float*)d_in[7];
    const float* Wl  = (const float*)d_in[8];
    const float* bl  = (const float*)d_in[9];
    float* out = (float*)d_out;

    // dtype detect + weight fold (one block)
    dwfold_kernel<<<1, 256>>>((const unsigned int*)eix, W1r, b1, W1o, W2r, b2, W2o, Wl, bl);

    // t1 = M1 x ; t2 = M2 x + v1 ; out = M3 x + c ; pack edges
    transform_kernel<<<3125, 256>>>(x, eix, out);

    // t2 += A t1 ; out += A t2   (4 lanes/edge, 4 edges/thread)
    scatter_kernel<0><<<3125, 256>>>(out);
    scatter_kernel<1><<<3125, 256>>>(out);
}

// round 13
// speedup vs baseline: 2.3427x; 1.0562x over previous
#include <cuda_runtime.h>
#include <cuda_bf16.h>

// Problem constants (fixed by the reference)
#define NNODES 50000
#define NEDGES 800000
#define D      64
#define NCLS   16

// Scratch (device globals)
__device__ float4 g_t1[NNODES * NCLS / 4];   // M1 x
__device__ float4 g_t2[NNODES * NCLS / 4];   // u2 + v1, then += A t1
__device__ float4 g_M4[3 * NCLS * D / 4];    // M1, M2, M3
__device__ float  g_v[2 * NCLS];             // v1, c
__device__ int    g_is64;                    // 1 if edge_index is int64
__device__ int2   g_edge2[NEDGES];           // packed (src, dst)

// ---------------------------------------------------------------------------
// Fused: dtype detect + unified weight fold. ONE block, 1024 threads
// (latency-bound kernel: more threads = fewer serial outputs per thread).
// ---------------------------------------------------------------------------
__global__ __launch_bounds__(1024) void dwfold_kernel(
        const unsigned int* __restrict__ widx,
        const float* __restrict__ W1r, const float* __restrict__ b1,
        const float* __restrict__ W1o, const float* __restrict__ W2r,
        const float* __restrict__ b2,  const float* __restrict__ W2o,
        const float* __restrict__ Wl,  const float* __restrict__ bl) {
    __shared__ float sWa[D * D];        // W2r then W1r
    __shared__ float sWb[D * D];        // W2o then W1o
    __shared__ float sWl[NCLS * D];
    __shared__ float sPr[NCLS * D];
    __shared__ float sPo[NCLS * D];
    __shared__ float sb1[D], sb2[D], sur[D], suo[D];
    __shared__ int any_nonzero;
    const int tid = threadIdx.x;

    // ---- dtype detect ----
    if (tid == 0) any_nonzero = 0;
    __syncthreads();
    {
        unsigned int acc = 0;
        for (int i = tid; i < 4096; i += 1024) acc |= widx[2 * i + 1];
        if (acc) any_nonzero = 1;
    }

    // ---- Phase 1 loads ----
    {
        const int nf4 = D * D / 4;                      // 1024
        for (int i = tid; i < nf4; i += 1024) {
            ((float4*)sWa)[i] = ((const float4*)W2r)[i];
            ((float4*)sWb)[i] = ((const float4*)W2o)[i];
        }
        if (tid < NCLS * D / 4)
            ((float4*)sWl)[tid] = ((const float4*)Wl)[tid];
        if (tid < D / 4) {
            ((float4*)sb1)[tid] = ((const float4*)b1)[tid];
            ((float4*)sb2)[tid] = ((const float4*)b2)[tid];
        }
    }
    __syncthreads();
    if (tid == 0) g_is64 = any_nonzero ? 0 : 1;

    if (tid < D) {
        float s = 0.f;
        for (int k = 0; k < D; k++) s += sWa[tid * D + k] * sb1[k];
        sur[tid] = s;
    } else if (tid < 2 * D) {
        const int m = tid - D;
        float s = 0.f;
        for (int k = 0; k < D; k++) s += sWb[m * D + k] * sb1[k];
        suo[m] = s;
    }

    // P_r, P_o : 1024 outputs, exactly one per thread
    {
        const int idx = tid;
        const int r = idx >> 6, m = idx & 63;
        float pr = 0.f, po = 0.f;
        for (int j = 0; j < D; j++) {
            const float w = sWl[r * D + j];
            pr += w * sWa[j * D + m];
            po += w * sWb[j * D + m];
        }
        sPr[idx] = pr;
        sPo[idx] = po;
    }
    __syncthreads();

    if (tid < NCLS) {
        float s = 0.f;
        for (int m = 0; m < D; m++) s += sWl[tid * D + m] * sur[m];
        g_v[tid] = s;
    } else if (tid < 2 * NCLS) {
        const int r = tid - NCLS;
        float s = 0.f;
        for (int m = 0; m < D; m++) s += sWl[r * D + m] * (suo[m] + sb2[m]);
        g_v[NCLS + r] = s + bl[r];
    }

    // ---- Phase 2 loads: W1r -> sWa, W1o -> sWb ----
    {
        const int nf4 = D * D / 4;
        for (int i = tid; i < nf4; i += 1024) {
            ((float4*)sWa)[i] = ((const float4*)W1r)[i];
            ((float4*)sWb)[i] = ((const float4*)W1o)[i];
        }
    }
    __syncthreads();

    // M1/M2/M3 : 3072 outputs, 3 per thread
    for (int idx = tid; idx < 3 * NCLS * D; idx += 1024) {
        const int which = idx / (NCLS * D);
        const int rem = idx - which * (NCLS * D);
        const int r = rem >> 6, k = rem & 63;
        float s = 0.f;
        if (which == 0) {
            for (int m = 0; m < D; m++) s += sPr[r * D + m] * sWa[m * D + k];
        } else if (which == 1) {
            for (int m = 0; m < D; m++)
                s += sPr[r * D + m] * sWb[m * D + k] + sPo[r * D + m] * sWa[m * D + k];
        } else {
            for (int m = 0; m < D; m++) s += sPo[r * D + m] * sWb[m * D + k];
        }
        ((float*)g_M4)[idx] = s;
    }
}

// ---------------------------------------------------------------------------
// transform: t1 = M1 x ; t2 = M2 x + v1 ; out = M3 x + c ; edge packing.
// LDS.128 inner loop, XOR-swizzled M tile. 16 nodes / 256-thread block.
// ---------------------------------------------------------------------------
__global__ __launch_bounds__(256) void transform_kernel(
        const float* __restrict__ x, const void* __restrict__ eidx,
        float* __restrict__ d_out) {
    __shared__ float4 sM4[3 * NCLS * 16];  // 768 float4 = 12 KB (swizzled)
    __shared__ float4 sx4[16 * 16];        // 256 float4 = 4 KB
    __shared__ float sv[2 * NCLS];
    const int tid = threadIdx.x;

    // Edge pack: issue index loads early; drains under the matvec below.
    const int e = blockIdx.x * 256 + tid;          // 3125*256 = 800000 exact
    int es, ed;
    if (g_is64) {
        const long long* ei = (const long long*)eidx;
        es = (int)ei[e];
        ed = (int)ei[NEDGES + e];
    } else {
        const int* ei = (const int*)eidx;
        es = ei[e];
        ed = ei[NEDGES + e];
    }

    if (tid < 2 * NCLS) sv[tid] = g_v[tid];
    for (int i = tid; i < 3 * NCLS * 16; i += 256) {
        const int row = i >> 4, k4 = i & 15;
        sM4[(row << 4) | (k4 ^ (row & 15))] = g_M4[i];
    }
    const int nodeBase = blockIdx.x * 16;
    sx4[tid] = ((const float4*)(x + (size_t)nodeBase * D))[tid];
    __syncthreads();

    const int j = tid >> 4;    // node within block
    const int r = tid & 15;    // class
    float a1 = 0.f, a2 = 0.f, a3 = 0.f;
    const float4* xb = &sx4[j << 4];
    #pragma unroll 4
    for (int k4 = 0; k4 < 16; k4++) {
        const float4 xv = xb[k4];
        const int sw = (r << 4) | (k4 ^ r);
        const float4 a = sM4[sw];
        const float4 b = sM4[256 + sw];
        const float4 c = sM4[512 + sw];
        a1 += a.x * xv.x + a.y * xv.y + a.z * xv.z + a.w * xv.w;
        a2 += b.x * xv.x + b.y * xv.y + b.z * xv.z + b.w * xv.w;
        a3 += c.x * xv.x + c.y * xv.y + c.z * xv.z + c.w * xv.w;
    }
    const int idx = (nodeBase + j) * NCLS + r;
    ((float*)g_t1)[idx] = a1;
    ((float*)g_t2)[idx] = a2 + sv[r];          // u2 + v1
    d_out[idx] = a3 + sv[NCLS + r];            // u3 + c
    g_edge2[e] = make_int2(es, ed);
}

// ---------------------------------------------------------------------------
// Scatter: 4 lanes/edge, 4 edges/thread grouped in ADJACENT PAIRS so each
// thread's index loads are 2x LDG.128 (int4 = 2 edges) instead of 4x LDG.64.
//   thread (g, c): edges 2g, 2g+1, 2g+E/2, 2g+1+E/2
//   PASS 0: g_t2[dst] += t1[src]      PASS 1: out[dst] += t2[src]
// ---------------------------------------------------------------------------
template <int PASS>
__global__ __launch_bounds__(256) void scatter_kernel(float* __restrict__ d_out) {
    const int t = blockIdx.x * 256 + threadIdx.x;   // 3125*256 = 800000 exact
    const int g = t >> 2;                           // pair group in [0, 200000)
    const int c = t & 3;                            // float4 component
    // Two int4 loads cover 4 edges (16B-aligned: even element index)
    const int4 p0 = ((const int4*)g_edge2)[g];                    // edges 2g, 2g+1
    const int4 p1 = ((const int4*)g_edge2)[g + NEDGES / 4];       // + E/2
    const float4* srcArr = (PASS == 0) ? g_t1 : g_t2;
    const float4 v0 = srcArr[p0.x * 4 + c];
    const float4 v1 = srcArr[p0.z * 4 + c];
    const float4 v2 = srcArr[p1.x * 4 + c];
    const float4 v3 = srcArr[p1.z * 4 + c];
    if (PASS == 0) {
        atomicAdd(&g_t2[p0.y * 4 + c], v0);
        atomicAdd(&g_t2[p0.w * 4 + c], v1);
        atomicAdd(&g_t2[p1.y * 4 + c], v2);
        atomicAdd(&g_t2[p1.w * 4 + c], v3);
    } else {
        atomicAdd((float4*)(d_out + p0.y * NCLS) + c, v0);
        atomicAdd((float4*)(d_out + p0.w * NCLS) + c, v1);
        atomicAdd((float4*)(d_out + p1.y * NCLS) + c, v2);
        atomicAdd((float4*)(d_out + p1.w * NCLS) + c, v3);
    }
}

// ---------------------------------------------------------------------------
extern "C" void kernel_launch(void* const* d_in, const int* in_sizes, int n_in,
                              void* d_out, int out_size) {
    const float* x   = (const float*)d_in[0];
    const void*  eix = d_in[1];
    const float* W1r = (const float*)d_in[2];
    const float* b1  = (const float*)d_in[3];
    const float* W1o = (const float*)d_in[4];
    const float* W2r = (const float*)d_in[5];
    const float* b2  = (const float*)d_in[6];
    const float* W2o = (const float*)d_in[7];
    const float* Wl  = (const float*)d_in[8];
    const float* bl  = (const float*)d_in[9];
    float* out = (float*)d_out;

    // dtype detect + weight fold (one block, 1024 threads)
    dwfold_kernel<<<1, 1024>>>((const unsigned int*)eix, W1r, b1, W1o, W2r, b2, W2o, Wl, bl);

    // t1 = M1 x ; t2 = M2 x + v1 ; out = M3 x + c ; pack edges
    transform_kernel<<<3125, 256>>>(x, eix, out);

    // t2 += A t1 ; out += A t2   (4 lanes/edge, 4 edges/thread)
    scatter_kernel<0><<<3125, 256>>>(out);
    scatter_kernel<1><<<3125, 256>>>(out);
}

// round 14
// speedup vs baseline: 2.8533x; 1.2179x over previous
#include <cuda_runtime.h>
#include <cuda_bf16.h>

// Problem constants (fixed by the reference)
#define NNODES 50000
#define NEDGES 800000
#define D      64
#define NCLS   16

// Scratch (device globals)
__device__ float4 g_t1[NNODES * NCLS / 4];   // M1 x
__device__ float4 g_t2[NNODES * NCLS / 4];   // u2 + v1, then += A t1
__device__ float4 g_M4[3 * NCLS * D / 4];    // M1, M2, M3
__device__ float  g_v[2 * NCLS];             // v1, c
__device__ int    g_is64;                    // 1 if edge_index is int64
__device__ int2   g_edge2[NEDGES];           // packed (src, dst)

// ---------------------------------------------------------------------------
// Fused: dtype detect + unified weight fold. ONE block, 1024 threads.
// ---------------------------------------------------------------------------
__global__ __launch_bounds__(1024) void dwfold_kernel(
        const unsigned int* __restrict__ widx,
        const float* __restrict__ W1r, const float* __restrict__ b1,
        const float* __restrict__ W1o, const float* __restrict__ W2r,
        const float* __restrict__ b2,  const float* __restrict__ W2o,
        const float* __restrict__ Wl,  const float* __restrict__ bl) {
    __shared__ float sWa[D * D];        // W2r then W1r
    __shared__ float sWb[D * D];        // W2o then W1o
    __shared__ float sWl[NCLS * D];
    __shared__ float sPr[NCLS * D];
    __shared__ float sPo[NCLS * D];
    __shared__ float sb1[D], sb2[D], sur[D], suo[D];
    __shared__ int any_nonzero;
    const int tid = threadIdx.x;

    // ---- dtype detect ----
    if (tid == 0) any_nonzero = 0;
    __syncthreads();
    {
        unsigned int acc = 0;
        for (int i = tid; i < 4096; i += 1024) acc |= widx[2 * i + 1];
        if (acc) any_nonzero = 1;
    }

    // ---- Phase 1 loads ----
    {
        const int nf4 = D * D / 4;                      // 1024
        for (int i = tid; i < nf4; i += 1024) {
            ((float4*)sWa)[i] = ((const float4*)W2r)[i];
            ((float4*)sWb)[i] = ((const float4*)W2o)[i];
        }
        if (tid < NCLS * D / 4)
            ((float4*)sWl)[tid] = ((const float4*)Wl)[tid];
        if (tid < D / 4) {
            ((float4*)sb1)[tid] = ((const float4*)b1)[tid];
            ((float4*)sb2)[tid] = ((const float4*)b2)[tid];
        }
    }
    __syncthreads();
    if (tid == 0) g_is64 = any_nonzero ? 0 : 1;

    if (tid < D) {
        float s = 0.f;
        for (int k = 0; k < D; k++) s += sWa[tid * D + k] * sb1[k];
        sur[tid] = s;
    } else if (tid < 2 * D) {
        const int m = tid - D;
        float s = 0.f;
        for (int k = 0; k < D; k++) s += sWb[m * D + k] * sb1[k];
        suo[m] = s;
    }

    // P_r, P_o : 1024 outputs, one per thread
    {
        const int r = tid >> 6, m = tid & 63;
        float pr = 0.f, po = 0.f;
        for (int j = 0; j < D; j++) {
            const float w = sWl[r * D + j];
            pr += w * sWa[j * D + m];
            po += w * sWb[j * D + m];
        }
        sPr[tid] = pr;
        sPo[tid] = po;
    }
    __syncthreads();

    if (tid < NCLS) {
        float s = 0.f;
        for (int m = 0; m < D; m++) s += sWl[tid * D + m] * sur[m];
        g_v[tid] = s;
    } else if (tid < 2 * NCLS) {
        const int r = tid - NCLS;
        float s = 0.f;
        for (int m = 0; m < D; m++) s += sWl[r * D + m] * (suo[m] + sb2[m]);
        g_v[NCLS + r] = s + bl[r];
    }

    // ---- Phase 2 loads: W1r -> sWa, W1o -> sWb ----
    {
        const int nf4 = D * D / 4;
        for (int i = tid; i < nf4; i += 1024) {
            ((float4*)sWa)[i] = ((const float4*)W1r)[i];
            ((float4*)sWb)[i] = ((const float4*)W1o)[i];
        }
    }
    __syncthreads();

    // M1/M2/M3 : 3072 outputs, 3 per thread
    for (int idx = tid; idx < 3 * NCLS * D; idx += 1024) {
        const int which = idx / (NCLS * D);
        const int rem = idx - which * (NCLS * D);
        const int r = rem >> 6, k = rem & 63;
        float s = 0.f;
        if (which == 0) {
            for (int m = 0; m < D; m++) s += sPr[r * D + m] * sWa[m * D + k];
        } else if (which == 1) {
            for (int m = 0; m < D; m++)
                s += sPr[r * D + m] * sWb[m * D + k] + sPo[r * D + m] * sWa[m * D + k];
        } else {
            for (int m = 0; m < D; m++) s += sPo[r * D + m] * sWb[m * D + k];
        }
        ((float*)g_M4)[idx] = s;
    }
}

// ---------------------------------------------------------------------------
// transform: t1 = M1 x ; t2 = M2 x + v1 ; out = M3 x + c ; edge packing.
// 4 NODES PER THREAD (64 per block): M smem reads amortized 4x -> FMA-bound.
// LDS.128 with XOR-swizzled M tile. Grid 782 (last block partial, guarded).
// ---------------------------------------------------------------------------
__global__ __launch_bounds__(256) void transform_kernel(
        const float* __restrict__ x, const void* __restrict__ eidx,
        float* __restrict__ d_out) {
    __shared__ float4 sM4[3 * NCLS * 16];  // 768 float4 = 12 KB (swizzled)
    __shared__ float4 sx4[64 * 16];        // 1024 float4 = 16 KB
    __shared__ float sv[2 * NCLS];
    const int tid = threadIdx.x;

    // Edge pack: 4 edges/thread, coalesced, guarded (782*1024 = 800768)
    {
        const int ebase = blockIdx.x * 1024 + tid;
        #pragma unroll
        for (int k = 0; k < 4; k++) {
            const int e = ebase + k * 256;
            if (e < NEDGES) {
                int es, ed;
                if (g_is64) {
                    const long long* ei = (const long long*)eidx;
                    es = (int)ei[e];
                    ed = (int)ei[NEDGES + e];
                } else {
                    const int* ei = (const int*)eidx;
                    es = ei[e];
                    ed = ei[NEDGES + e];
                }
                g_edge2[e] = make_int2(es, ed);
            }
        }
    }

    if (tid < 2 * NCLS) sv[tid] = g_v[tid];
    for (int i = tid; i < 3 * NCLS * 16; i += 256) {
        const int row = i >> 4, k4 = i & 15;
        sM4[(row << 4) | (k4 ^ (row & 15))] = g_M4[i];
    }
    // x tile: 64 nodes x 16 float4 = 1024 f4; 4 per thread; guard global range
    {
        const int gbase = blockIdx.x * 1024;
        #pragma unroll
        for (int k = 0; k < 4; k++) {
            const int i = tid + k * 256;
            const int gi = gbase + i;
            sx4[i] = (gi < NNODES * 16) ? ((const float4*)x)[gi]
                                        : make_float4(0.f, 0.f, 0.f, 0.f);
        }
    }
    __syncthreads();

    const int slot = tid >> 4;   // 0..15 -> 4 nodes each
    const int r = tid & 15;      // class
    float a1[4] = {0.f, 0.f, 0.f, 0.f};
    float a2[4] = {0.f, 0.f, 0.f, 0.f};
    float a3[4] = {0.f, 0.f, 0.f, 0.f};
    #pragma unroll 4
    for (int k4 = 0; k4 < 16; k4++) {
        const int sw = (r << 4) | (k4 ^ r);
        const float4 a = sM4[sw];
        const float4 b = sM4[256 + sw];
        const float4 c = sM4[512 + sw];
        #pragma unroll
        for (int q = 0; q < 4; q++) {
            const float4 xv = sx4[(slot * 4 + q) * 16 + k4];
            a1[q] += a.x * xv.x + a.y * xv.y + a.z * xv.z + a.w * xv.w;
            a2[q] += b.x * xv.x + b.y * xv.y + b.z * xv.z + b.w * xv.w;
            a3[q] += c.x * xv.x + c.y * xv.y + c.z * xv.z + c.w * xv.w;
        }
    }
    const int nodeBase = blockIdx.x * 64 + slot * 4;
    #pragma unroll
    for (int q = 0; q < 4; q++) {
        const int n = nodeBase + q;
        if (n < NNODES) {
            const int idx = n * NCLS + r;
            ((float*)g_t1)[idx] = a1[q];
            ((float*)g_t2)[idx] = a2[q] + sv[r];          // u2 + v1
            d_out[idx] = a3[q] + sv[NCLS + r];            // u3 + c
        }
    }
}

// ---------------------------------------------------------------------------
// Scatter: 4 lanes/edge, 4 edges/thread, index loads as 2x LDG.128.
//   PASS 0: g_t2[dst] += t1[src]      PASS 1: out[dst] += t2[src]
// ---------------------------------------------------------------------------
template <int PASS>
__global__ __launch_bounds__(256) void scatter_kernel(float* __restrict__ d_out) {
    const int t = blockIdx.x * 256 + threadIdx.x;   // 3125*256 = 800000 exact
    const int g = t >> 2;                           // pair group in [0, 200000)
    const int c = t & 3;                            // float4 component
    const int4 p0 = ((const int4*)g_edge2)[g];                    // edges 2g, 2g+1
    const int4 p1 = ((const int4*)g_edge2)[g + NEDGES / 4];       // + E/2
    const float4* srcArr = (PASS == 0) ? g_t1 : g_t2;
    const float4 v0 = srcArr[p0.x * 4 + c];
    const float4 v1 = srcArr[p0.z * 4 + c];
    const float4 v2 = srcArr[p1.x * 4 + c];
    const float4 v3 = srcArr[p1.z * 4 + c];
    if (PASS == 0) {
        atomicAdd(&g_t2[p0.y * 4 + c], v0);
        atomicAdd(&g_t2[p0.w * 4 + c], v1);
        atomicAdd(&g_t2[p1.y * 4 + c], v2);
        atomicAdd(&g_t2[p1.w * 4 + c], v3);
    } else {
        atomicAdd((float4*)(d_out + p0.y * NCLS) + c, v0);
        atomicAdd((float4*)(d_out + p0.w * NCLS) + c, v1);
        atomicAdd((float4*)(d_out + p1.y * NCLS) + c, v2);
        atomicAdd((float4*)(d_out + p1.w * NCLS) + c, v3);
    }
}

// ---------------------------------------------------------------------------
extern "C" void kernel_launch(void* const* d_in, const int* in_sizes, int n_in,
                              void* d_out, int out_size) {
    const float* x   = (const float*)d_in[0];
    const void*  eix = d_in[1];
    const float* W1r = (const float*)d_in[2];
    const float* b1  = (const float*)d_in[3];
    const float* W1o = (const float*)d_in[4];
    const float* W2r = (const float*)d_in[5];
    const float* b2  = (const float*)d_in[6];
    const float* W2o = (const float*)d_in[7];
    const float* Wl  = (const float*)d_in[8];
    const float* bl  = (const float*)d_in[9];
    float* out = (float*)d_out;

    // dtype detect + weight fold (one block, 1024 threads)
    dwfold_kernel<<<1, 1024>>>((const unsigned int*)eix, W1r, b1, W1o, W2r, b2, W2o, Wl, bl);

    // t1 = M1 x ; t2 = M2 x + v1 ; out = M3 x + c ; pack edges (64 nodes/block)
    transform_kernel<<<782, 256>>>(x, eix, out);

    // t2 += A t1 ; out += A t2   (4 lanes/edge, 4 edges/thread)
    scatter_kernel<0><<<3125, 256>>>(out);
    scatter_kernel<1><<<3125, 256>>>(out);
}